// round 12
// baseline (speedup 1.0000x reference)
#include <cuda_runtime.h>
#include <cuda_fp16.h>
#include <math.h>

#define BB 2
#define SS 2048
#define DD 1024
#define HH 16
#define HD 64
#define M1 (BB*SS)      // 4096
#define N1 (3*DD)       // 3072
#define KD DD           // 1024
#define NBH (BB*HH)     // 32
#define SCALE 0.125f
#define LOG2E 1.44269504088896340736f
// fixed softmax shift: |q.k| <= 1 (unit vectors) -> |score*log2e| <= SCALE*LOG2E
#define M0 (SCALE * LOG2E)

// ---------------- scratch (device globals; no allocations allowed) ----------
__device__ __half g_qkv[(size_t)M1 * N1];
__device__ __half g_q[(size_t)NBH * SS * HD];   // fp16, pre-scaled SCALE*log2e
__device__ __half g_k[(size_t)NBH * SS * HD];
__device__ __half g_v[(size_t)NBH * HD * SS];   // [bh][d][s] fp16 (transposed)
__device__ __half g_ao[(size_t)BB * SS * DD];
__device__ __half g_tokh[(size_t)M1 * KD];
__device__ __half g_wh[(size_t)N1 * KD];
__device__ __half g_owh[(size_t)DD * DD];
__device__ float2 g_sc[SS * 32];                // RoPE (sin, cos) table

// ---------------- helpers ----------------------------------------------------
__device__ __forceinline__ float ex2(float x) {
    float y;
    asm("ex2.approx.ftz.f32 %0, %1;" : "=f"(y) : "f"(x));
    return y;
}
__device__ __forceinline__ unsigned pack_h2(float lo, float hi) {
    __half2 h = __floats2half2_rn(lo, hi);
    return *(unsigned*)&h;
}
__device__ __forceinline__ void mma_f16(float* c,
    unsigned a0, unsigned a1, unsigned a2, unsigned a3,
    unsigned b0, unsigned b1)
{
    asm volatile(
        "mma.sync.aligned.m16n8k16.row.col.f32.f16.f16.f32 "
        "{%0,%1,%2,%3},{%4,%5,%6,%7},{%8,%9},{%0,%1,%2,%3};"
        : "+f"(c[0]), "+f"(c[1]), "+f"(c[2]), "+f"(c[3])
        : "r"(a0), "r"(a1), "r"(a2), "r"(a3), "r"(b0), "r"(b1));
}
__device__ __forceinline__ void cp16(unsigned s, const void* g) {
    asm volatile("cp.async.cg.shared.global [%0], [%1], 16;" :: "r"(s), "l"(g));
}
__device__ __forceinline__ void cp_commit() {
    asm volatile("cp.async.commit_group;");
}
template<int N> __device__ __forceinline__ void cp_wait() {
    asm volatile("cp.async.wait_group %0;" :: "n"(N));
}
#define LDSM4(r0, r1, r2, r3, addr) \
    asm volatile("ldmatrix.sync.aligned.m8n8.x4.shared.b16 {%0,%1,%2,%3}, [%4];" \
        : "=r"(r0), "=r"(r1), "=r"(r2), "=r"(r3) : "r"(addr))

// ---------------- RoPE sin/cos table ----------------------------------------
__global__ void sincos_table_kernel()
{
    const int idx = blockIdx.x * blockDim.x + threadIdx.x;  // 0..65535
    const int s = idx >> 5;
    const int f = idx & 31;
    double invd = exp(-(double)f * (9.210340371976184 / 32.0));
    float theta = (float)((double)s * invd);
    float sn, cs;
    sincosf(theta, &sn, &cs);
    g_sc[idx] = make_float2(sn, cs);
}

// ---------------- fp16 conversion pass: 3 tensors in one launch -------------
__global__ void tohalf3_kernel(const float4* s0, __half2* d0, int n0,
                               const float4* s1, __half2* d1, int n1,
                               const float4* s2, __half2* d2, int n2)
{
    const int total = n0 + n1 + n2;
    for (int i = blockIdx.x * blockDim.x + threadIdx.x; i < total;
         i += gridDim.x * blockDim.x) {
        const float4* s; __half2* d; int j = i;
        if (j < n0) { s = s0; d = d0; }
        else if ((j -= n0) < n1) { s = s1; d = d1; }
        else { j -= n1; s = s2; d = d2; }
        float4 v = s[j];
        d[2 * j]     = __floats2half2_rn(v.x, v.y);
        d[2 * j + 1] = __floats2half2_rn(v.z, v.w);
    }
}

// ---------------- fp16 GEMM: BK=64, 3-stage cp.async, ldmatrix --------------
#define GKP 72
#define GSTG (128 * GKP * 2)
#define GEMM_SMEM (3 * 2 * GSTG)              // 110592 B

template<bool HALF_OUT>
__global__ __launch_bounds__(256, 2) void gemm_f16_ldsm(
    const __half* __restrict__ A, const __half* __restrict__ W,
    const float* __restrict__ bias, void* __restrict__ Cv,
    int M, int N, int K)
{
    extern __shared__ __align__(16) unsigned gsm[];
    const unsigned sA_u = (unsigned)__cvta_generic_to_shared(gsm);
    const unsigned sB_u = sA_u + 3 * GSTG;

    const int tid = threadIdx.x;
    const int bm = blockIdx.y << 7;
    const int bn = blockIdx.x << 7;
    const int w = tid >> 5;
    const int lane = tid & 31;
    const int wm = (w & 1) << 6;
    const int wn = (w >> 1) << 5;
    const int fr = lane >> 2;
    const int fc = lane & 3;

    const int lrow = tid >> 1;
    const int lc4 = (tid & 1) << 2;
    const __half* Asrc = A + (size_t)(bm + lrow) * K;
    const __half* Wsrc = W + (size_t)(bn + lrow) * K;
    const unsigned dA0 = sA_u + lrow * GKP * 2;
    const unsigned dB0 = sB_u + lrow * GKP * 2;

    const unsigned a_off = ((wm + (lane & 15)) * GKP + ((lane >> 4) << 3)) * 2;
    const unsigned b_off = (((lane & 7) + ((lane >> 4) << 3) + wn) * GKP
                            + (((lane >> 3) & 1) << 3)) * 2;

    float acc[4][4][4];
#pragma unroll
    for (int mt = 0; mt < 4; mt++)
#pragma unroll
        for (int nt = 0; nt < 4; nt++)
#pragma unroll
            for (int i = 0; i < 4; i++) acc[mt][nt][i] = 0.f;

    const int nk = K >> 6;
    auto issue = [&](int kt) {
        const unsigned so = (kt % 3) * GSTG;
        const __half* a = Asrc + ((size_t)kt << 6);
        const __half* b = Wsrc + ((size_t)kt << 6);
#pragma unroll
        for (int t = 0; t < 4; t++) {
            const int c = (lc4 + t) << 3;
            cp16(dA0 + so + c * 2, a + c);
            cp16(dB0 + so + c * 2, b + c);
        }
        cp_commit();
    };

    issue(0); issue(1);

    for (int kt = 0; kt < nk; kt++) {
        if (kt + 1 < nk) cp_wait<1>(); else cp_wait<0>();
        __syncthreads();
        if (kt + 2 < nk) issue(kt + 2);

        const unsigned sa = sA_u + (kt % 3) * GSTG;
        const unsigned sb = sB_u + (kt % 3) * GSTG;
#pragma unroll
        for (int ks = 0; ks < 4; ks++) {
            const unsigned kbb = ks * 32;
            unsigned af[4][4], bf[4][2];
#pragma unroll
            for (int mt = 0; mt < 4; mt++)
                LDSM4(af[mt][0], af[mt][1], af[mt][2], af[mt][3],
                      sa + a_off + mt * (16 * GKP * 2) + kbb);
#pragma unroll
            for (int p = 0; p < 2; p++)
                LDSM4(bf[2*p][0], bf[2*p][1], bf[2*p+1][0], bf[2*p+1][1],
                      sb + b_off + p * (16 * GKP * 2) + kbb);
#pragma unroll
            for (int mt = 0; mt < 4; mt++)
#pragma unroll
                for (int nt = 0; nt < 4; nt++)
                    mma_f16(acc[mt][nt], af[mt][0], af[mt][1], af[mt][2], af[mt][3],
                            bf[nt][0], bf[nt][1]);
        }
    }

#pragma unroll
    for (int mt = 0; mt < 4; mt++) {
        const int row = bm + wm + (mt << 4) + fr;
#pragma unroll
        for (int nt = 0; nt < 4; nt++) {
            const int col = bn + wn + (nt << 3) + (fc << 1);
            const float b0 = bias[col], b1 = bias[col + 1];
            if (HALF_OUT) {
                __half* C = (__half*)Cv;
                *(__half2*)(C + (size_t)row * N + col) =
                    __floats2half2_rn(acc[mt][nt][0] + b0, acc[mt][nt][1] + b1);
                *(__half2*)(C + (size_t)(row + 8) * N + col) =
                    __floats2half2_rn(acc[mt][nt][2] + b0, acc[mt][nt][3] + b1);
            } else {
                float* C = (float*)Cv;
                *(float2*)(C + (size_t)row * N + col) =
                    make_float2(acc[mt][nt][0] + b0, acc[mt][nt][1] + b1);
                *(float2*)(C + (size_t)(row + 8) * N + col) =
                    make_float2(acc[mt][nt][2] + b0, acc[mt][nt][3] + b1);
            }
        }
    }
}

// ---------------- RoPE + L2-norm + fp16 q/k + fp16 V transpose --------------
// sin/cos from precomputed table (no MUFU/DFMA in the hot loop).
__global__ __launch_bounds__(128) void rope_kernel()
{
    __shared__ float sVt[64][65];
    const int tid = threadIdx.x;
    const int w = tid >> 5;
    const int f = tid & 31;
    const int blk = blockIdx.x;
    const int bh = blk >> 5;
    const int s0 = (blk & 31) << 6;
    const int b = bh >> 4, h = bh & 15;

#pragma unroll 1
    for (int t = 0; t < 16; t++) {
        const int sl = (w << 4) + t;
        const int s = s0 + sl;
        const float2 sc = g_sc[(s << 5) + f];
        const float sn = sc.x, cs = sc.y;

        const __half* src = g_qkv + (size_t)(b * SS + s) * N1 + h * HD;
        float2 qv = __half22float2(*(const __half2*)(src + 2 * f));
        float2 kv = __half22float2(*(const __half2*)(src + DD + 2 * f));
        float2 vv = __half22float2(*(const __half2*)(src + 2 * DD + 2 * f));

        const size_t dst = ((size_t)bh * SS + s) * HD + 2 * f;
        {
            float re = qv.x * cs - qv.y * sn;
            float ro = qv.x * sn + qv.y * cs;
            float sq = re * re + ro * ro;
#pragma unroll
            for (int msk = 16; msk > 0; msk >>= 1) sq += __shfl_xor_sync(0xffffffffu, sq, msk);
            float inv = (SCALE * LOG2E) / fmaxf(sqrtf(sq), 1e-12f);
            *(__half2*)(g_q + dst) = __floats2half2_rn(re * inv, ro * inv);
        }
        {
            float re = kv.x * cs - kv.y * sn;
            float ro = kv.x * sn + kv.y * cs;
            float sq = re * re + ro * ro;
#pragma unroll
            for (int msk = 16; msk > 0; msk >>= 1) sq += __shfl_xor_sync(0xffffffffu, sq, msk);
            float inv = 1.0f / fmaxf(sqrtf(sq), 1e-12f);
            *(__half2*)(g_k + dst) = __floats2half2_rn(re * inv, ro * inv);
        }
        sVt[sl][2 * f]     = vv.x;
        sVt[sl][2 * f + 1] = vv.y;
    }
    __syncthreads();

#pragma unroll 1
    for (int t = 0; t < 16; t++) {
        const int d = (w << 4) + t;
        __half* dst = g_v + ((size_t)bh * HD + d) * SS + s0;
        dst[f]      = __float2half_rn(sVt[f][d]);
        dst[f + 32] = __float2half_rn(sVt[f + 32][d]);
    }
}

// ---------------- flash attention: fixed-max softmax, 128-kv barrier tiles --
// 2 stages of 128-kv each; two 64-kv halves per barrier (16 barriers total).
// sK: [kv=128][d=64] pitch 72h. sV: [d=64][s=128] pitch 136h. sQ pitch 72h.
#define KP2 72
#define VP2 136
#define KSTG2 (128 * KP2 * 2)                // 18432 B
#define VSTG2 (64 * VP2 * 2)                 // 17408 B
#define QSTG (128 * KP2 * 2)                 // 18432 B
#define ATTN_SMEM (2 * (KSTG2 + VSTG2) + QSTG)   // 90112 B

__global__ __launch_bounds__(256, 2) void attn_f16(__half* __restrict__ Oo)
{
    extern __shared__ __align__(16) unsigned smem_[];
    const unsigned sK_u = (unsigned)__cvta_generic_to_shared(smem_);
    const unsigned sV_u = sK_u + 2 * KSTG2;
    const unsigned sQ_u = sV_u + 2 * VSTG2;

    const int tid = threadIdx.x;
    const int w = tid >> 5;
    const int lane = tid & 31;
    const int fr = lane >> 2;
    const int fc = lane & 3;
    const int bh = blockIdx.y;
    const int b = bh >> 4, h = bh & 15;
    const int q0 = blockIdx.x << 7;

    const __half* Qp = g_q + (size_t)bh * SS * HD;
    const __half* Kp = g_k + (size_t)bh * SS * HD;
    const __half* Vp = g_v + (size_t)bh * HD * SS;

    // loader coords
    const int krow = tid >> 1;               // 0..127 (K rows)
    const int kc = tid & 1;                  // 2 threads per K row
    const int vrow = tid >> 2;               // 0..63 (V rows = d)
    const int vc = tid & 3;                  // 4 threads per V row
    const int qrow = tid >> 1;               // 0..127
    const int qc = tid & 1;

    auto issueKV = [&](int jt2) {            // jt2: 128-kv tile index, 0..15
        const unsigned soK = sK_u + (jt2 & 1) * KSTG2;
        const unsigned soV = sV_u + (jt2 & 1) * VSTG2;
        const __half* gK = Kp + (size_t)(jt2 * 128 + krow) * HD;
        const __half* gV = Vp + (size_t)vrow * SS + jt2 * 128;
#pragma unroll
        for (int t = 0; t < 4; t++) {
            const int ck = ((kc << 2) + t) << 3;     // 0..56 halves
            cp16(soK + (krow * KP2 + ck) * 2, gK + ck);
            const int cv = ((vc << 2) + t) << 3;     // 0..120 halves
            cp16(soV + (vrow * VP2 + cv) * 2, gV + cv);
        }
        cp_commit();
    };

    // stage Q, prefetch KV tile 0
    {
        const __half* gQ = Qp + (size_t)(q0 + qrow) * HD;
#pragma unroll
        for (int t = 0; t < 4; t++) {
            const int c = ((qc << 2) + t) << 3;
            cp16(sQ_u + (qrow * KP2 + c) * 2, gQ + c);
        }
        cp_commit();
    }
    issueKV(0);

    cp_wait<1>();      // Q resident (KV0 may still be in flight)
    __syncthreads();

    const unsigned a_q_off = (((w << 4) + (lane & 15)) * KP2 + ((lane >> 4) << 3)) * 2;
    unsigned qf[4][4];
#pragma unroll
    for (int ks = 0; ks < 4; ks++)
        LDSM4(qf[ks][0], qf[ks][1], qf[ks][2], qf[ks][3], sQ_u + a_q_off + ks * 32);

    const unsigned kb_off = (((lane & 7) + ((lane >> 4) << 3)) * KP2
                             + (((lane >> 3) & 1) << 3)) * 2;
    const unsigned vb_off = (((lane & 7) + ((lane >> 4) << 3)) * VP2
                             + (((lane >> 3) & 1) << 3)) * 2;

    float o[8][4];
#pragma unroll
    for (int nt = 0; nt < 8; nt++)
#pragma unroll
        for (int i = 0; i < 4; i++) o[nt][i] = 0.f;
    float lA = 0.f, lB = 0.f;     // plain row sums (fixed shift -> no max state)

    const int NT2 = SS / 128;    // 16 barrier tiles
    for (int jt2 = 0; jt2 < NT2; jt2++) {
        cp_wait<0>();
        __syncthreads();
        if (jt2 + 1 < NT2) issueKV(jt2 + 1);

        const unsigned Kst = sK_u + (jt2 & 1) * KSTG2;
        const unsigned Vst = sV_u + (jt2 & 1) * VSTG2;

#pragma unroll
        for (int hh = 0; hh < 2; hh++) {
            const unsigned Ktu = Kst + hh * (64 * KP2 * 2);
            const unsigned Vtu = Vst + hh * (64 * 2);     // column offset 64 halves

            // S = Q K^T
            float s[8][4];
#pragma unroll
            for (int nt = 0; nt < 8; nt++)
#pragma unroll
                for (int i = 0; i < 4; i++) s[nt][i] = 0.f;
#pragma unroll
            for (int ks = 0; ks < 4; ks++) {
                unsigned bf[8][2];
#pragma unroll
                for (int ng = 0; ng < 4; ng++)
                    LDSM4(bf[2*ng][0], bf[2*ng][1], bf[2*ng+1][0], bf[2*ng+1][1],
                          Ktu + kb_off + ng * (16 * KP2 * 2) + ks * 32);
#pragma unroll
                for (int nt = 0; nt < 8; nt++)
                    mma_f16(s[nt], qf[ks][0], qf[ks][1], qf[ks][2], qf[ks][3],
                            bf[nt][0], bf[nt][1]);
            }

            // p = exp2(s - M0); accumulate row sums
#pragma unroll
            for (int nt = 0; nt < 8; nt++) {
                s[nt][0] = ex2(s[nt][0] - M0);
                s[nt][1] = ex2(s[nt][1] - M0);
                s[nt][2] = ex2(s[nt][2] - M0);
                s[nt][3] = ex2(s[nt][3] - M0);
                lA += s[nt][0] + s[nt][1];
                lB += s[nt][2] + s[nt][3];
            }

            // O += P @ V : P stays in registers (C-frag == A-frag)
#pragma unroll
            for (int ks = 0; ks < 4; ks++) {
                const unsigned a0 = pack_h2(s[2*ks][0],   s[2*ks][1]);
                const unsigned a1 = pack_h2(s[2*ks][2],   s[2*ks][3]);
                const unsigned a2 = pack_h2(s[2*ks+1][0], s[2*ks+1][1]);
                const unsigned a3 = pack_h2(s[2*ks+1][2], s[2*ks+1][3]);
                unsigned vf[8][2];
#pragma unroll
                for (int p = 0; p < 4; p++)
                    LDSM4(vf[2*p][0], vf[2*p][1], vf[2*p+1][0], vf[2*p+1][1],
                          Vtu + vb_off + p * (16 * VP2 * 2) + ks * 32);
#pragma unroll
                for (int nt = 0; nt < 8; nt++)
                    mma_f16(o[nt], a0, a1, a2, a3, vf[nt][0], vf[nt][1]);
            }
        }
    }

    // epilogue: deferred row-sum reduction, normalize, write fp16
    lA += __shfl_xor_sync(0xffffffffu, lA, 1);
    lA += __shfl_xor_sync(0xffffffffu, lA, 2);
    lB += __shfl_xor_sync(0xffffffffu, lB, 1);
    lB += __shfl_xor_sync(0xffffffffu, lB, 2);
    const float invA = 1.0f / lA;
    const float invB = 1.0f / lB;
    __half* Op = Oo + (size_t)b * SS * DD + h * HD;
    const int ra = q0 + (w << 4) + fr;
#pragma unroll
    for (int nt = 0; nt < 8; nt++) {
        const int col = (nt << 3) + (fc << 1);
        *(__half2*)(Op + (size_t)ra * DD + col) =
            __floats2half2_rn(o[nt][0] * invA, o[nt][1] * invA);
        *(__half2*)(Op + (size_t)(ra + 8) * DD + col) =
            __floats2half2_rn(o[nt][2] * invB, o[nt][3] * invB);
    }
}

// ---------------- launch ----------------------------------------------------
extern "C" void kernel_launch(void* const* d_in, const int* in_sizes, int n_in,
                              void* d_out, int out_size)
{
    (void)in_sizes; (void)n_in; (void)out_size;
    const float* tokens = (const float*)d_in[0];
    const float* qkv_w  = (const float*)d_in[1];
    const float* qkv_b  = (const float*)d_in[2];
    const float* out_w  = (const float*)d_in[3];
    const float* out_b  = (const float*)d_in[4];
    float* out = (float*)d_out;

    __half *qkv_s, *ao_s, *tokh, *wh, *owh;
    cudaGetSymbolAddress((void**)&qkv_s, g_qkv);
    cudaGetSymbolAddress((void**)&ao_s, g_ao);
    cudaGetSymbolAddress((void**)&tokh, g_tokh);
    cudaGetSymbolAddress((void**)&wh, g_wh);
    cudaGetSymbolAddress((void**)&owh, g_owh);

    static int smem_set = 0;
    if (!smem_set) {
        cudaFuncSetAttribute(gemm_f16_ldsm<true>, cudaFuncAttributeMaxDynamicSharedMemorySize, GEMM_SMEM);
        cudaFuncSetAttribute(gemm_f16_ldsm<false>, cudaFuncAttributeMaxDynamicSharedMemorySize, GEMM_SMEM);
        cudaFuncSetAttribute(attn_f16, cudaFuncAttributeMaxDynamicSharedMemorySize, ATTN_SMEM);
        smem_set = 1;
    }

    // 0) sin/cos table + fp16 operand conversion (independent, back to back)
    sincos_table_kernel<<<256, 256>>>();
    tohalf3_kernel<<<2048, 256>>>(
        (const float4*)tokens, (__half2*)tokh, M1 * KD / 4,
        (const float4*)qkv_w,  (__half2*)wh,   N1 * KD / 4,
        (const float4*)out_w,  (__half2*)owh,  DD * DD / 4);

    // 1) QKV projection
    gemm_f16_ldsm<true><<<dim3(N1 / 128, M1 / 128), 256, GEMM_SMEM>>>(
        tokh, wh, qkv_b, qkv_s, M1, N1, KD);
    // 2) RoPE (table) + normalize (+SCALE*log2e on q) + fp16 q/k/v + V transpose
    rope_kernel<<<NBH * (SS / 64), 128>>>();
    // 3) flash attention (fixed-max softmax, 128-kv barrier tiles)
    attn_f16<<<dim3(SS / 128, NBH), 256, ATTN_SMEM>>>(ao_s);
    // 4) output projection
    gemm_f16_ldsm<false><<<dim3(DD / 128, M1 / 128), 256, GEMM_SMEM>>>(
        ao_s, owh, out_b, out, M1, DD, KD);
}

// round 13
// speedup vs baseline: 1.0777x; 1.0777x over previous
#include <cuda_runtime.h>
#include <cuda_fp16.h>
#include <math.h>

#define BB 2
#define SS 2048
#define DD 1024
#define HH 16
#define HD 64
#define M1 (BB*SS)      // 4096
#define N1 (3*DD)       // 3072
#define KD DD           // 1024
#define NBH (BB*HH)     // 32
#define SCALE 0.125f
#define LOG2E 1.44269504088896340736f
// fixed softmax shift: |q.k| <= 1 (unit vectors) -> |score*log2e| <= SCALE*LOG2E
#define M0 (SCALE * LOG2E)

// ---------------- scratch (device globals; no allocations allowed) ----------
__device__ __half g_qkv[(size_t)M1 * N1];
__device__ __half g_q[(size_t)NBH * SS * HD];   // fp16, pre-scaled SCALE*log2e
__device__ __half g_k[(size_t)NBH * SS * HD];
__device__ __half g_v[(size_t)NBH * HD * SS];   // [bh][d][s] fp16 (transposed)
__device__ __half g_ao[(size_t)BB * SS * DD];
__device__ __half g_tokh[(size_t)M1 * KD];
__device__ __half g_wh[(size_t)N1 * KD];
__device__ __half g_owh[(size_t)DD * DD];
__device__ float2 g_sc[SS * 32];                // RoPE (sin, cos) table

// ---------------- helpers ----------------------------------------------------
__device__ __forceinline__ float ex2(float x) {
    float y;
    asm("ex2.approx.ftz.f32 %0, %1;" : "=f"(y) : "f"(x));
    return y;
}
__device__ __forceinline__ unsigned pack_h2(float lo, float hi) {
    __half2 h = __floats2half2_rn(lo, hi);
    return *(unsigned*)&h;
}
__device__ __forceinline__ void mma_f16(float* c,
    unsigned a0, unsigned a1, unsigned a2, unsigned a3,
    unsigned b0, unsigned b1)
{
    asm volatile(
        "mma.sync.aligned.m16n8k16.row.col.f32.f16.f16.f32 "
        "{%0,%1,%2,%3},{%4,%5,%6,%7},{%8,%9},{%0,%1,%2,%3};"
        : "+f"(c[0]), "+f"(c[1]), "+f"(c[2]), "+f"(c[3])
        : "r"(a0), "r"(a1), "r"(a2), "r"(a3), "r"(b0), "r"(b1));
}
__device__ __forceinline__ void cp16(unsigned s, const void* g) {
    asm volatile("cp.async.cg.shared.global [%0], [%1], 16;" :: "r"(s), "l"(g));
}
__device__ __forceinline__ void cp_commit() {
    asm volatile("cp.async.commit_group;");
}
template<int N> __device__ __forceinline__ void cp_wait() {
    asm volatile("cp.async.wait_group %0;" :: "n"(N));
}
#define LDSM4(r0, r1, r2, r3, addr) \
    asm volatile("ldmatrix.sync.aligned.m8n8.x4.shared.b16 {%0,%1,%2,%3}, [%4];" \
        : "=r"(r0), "=r"(r1), "=r"(r2), "=r"(r3) : "r"(addr))

// ---------------- RoPE sin/cos table ----------------------------------------
__global__ void sincos_table_kernel()
{
    const int idx = blockIdx.x * blockDim.x + threadIdx.x;  // 0..65535
    const int s = idx >> 5;
    const int f = idx & 31;
    double invd = exp(-(double)f * (9.210340371976184 / 32.0));
    float theta = (float)((double)s * invd);
    float sn, cs;
    sincosf(theta, &sn, &cs);
    g_sc[idx] = make_float2(sn, cs);
}

// ---------------- fp16 conversion pass: 3 tensors in one launch -------------
__global__ void tohalf3_kernel(const float4* s0, __half2* d0, int n0,
                               const float4* s1, __half2* d1, int n1,
                               const float4* s2, __half2* d2, int n2)
{
    const int total = n0 + n1 + n2;
    for (int i = blockIdx.x * blockDim.x + threadIdx.x; i < total;
         i += gridDim.x * blockDim.x) {
        const float4* s; __half2* d; int j = i;
        if (j < n0) { s = s0; d = d0; }
        else if ((j -= n0) < n1) { s = s1; d = d1; }
        else { j -= n1; s = s2; d = d2; }
        float4 v = s[j];
        d[2 * j]     = __floats2half2_rn(v.x, v.y);
        d[2 * j + 1] = __floats2half2_rn(v.z, v.w);
    }
}

// ---------------- fp16 GEMM: BK=64, 3-stage cp.async, ldmatrix --------------
#define GKP 72
#define GSTG (128 * GKP * 2)
#define GEMM_SMEM (3 * 2 * GSTG)              // 110592 B

template<bool HALF_OUT>
__global__ __launch_bounds__(256, 2) void gemm_f16_ldsm(
    const __half* __restrict__ A, const __half* __restrict__ W,
    const float* __restrict__ bias, void* __restrict__ Cv,
    int M, int N, int K)
{
    extern __shared__ __align__(16) unsigned gsm[];
    const unsigned sA_u = (unsigned)__cvta_generic_to_shared(gsm);
    const unsigned sB_u = sA_u + 3 * GSTG;

    const int tid = threadIdx.x;
    const int bm = blockIdx.y << 7;
    const int bn = blockIdx.x << 7;
    const int w = tid >> 5;
    const int lane = tid & 31;
    const int wm = (w & 1) << 6;
    const int wn = (w >> 1) << 5;
    const int fr = lane >> 2;
    const int fc = lane & 3;

    const int lrow = tid >> 1;
    const int lc4 = (tid & 1) << 2;
    const __half* Asrc = A + (size_t)(bm + lrow) * K;
    const __half* Wsrc = W + (size_t)(bn + lrow) * K;
    const unsigned dA0 = sA_u + lrow * GKP * 2;
    const unsigned dB0 = sB_u + lrow * GKP * 2;

    const unsigned a_off = ((wm + (lane & 15)) * GKP + ((lane >> 4) << 3)) * 2;
    const unsigned b_off = (((lane & 7) + ((lane >> 4) << 3) + wn) * GKP
                            + (((lane >> 3) & 1) << 3)) * 2;

    float acc[4][4][4];
#pragma unroll
    for (int mt = 0; mt < 4; mt++)
#pragma unroll
        for (int nt = 0; nt < 4; nt++)
#pragma unroll
            for (int i = 0; i < 4; i++) acc[mt][nt][i] = 0.f;

    const int nk = K >> 6;
    auto issue = [&](int kt) {
        const unsigned so = (kt % 3) * GSTG;
        const __half* a = Asrc + ((size_t)kt << 6);
        const __half* b = Wsrc + ((size_t)kt << 6);
#pragma unroll
        for (int t = 0; t < 4; t++) {
            const int c = (lc4 + t) << 3;
            cp16(dA0 + so + c * 2, a + c);
            cp16(dB0 + so + c * 2, b + c);
        }
        cp_commit();
    };

    issue(0); issue(1);

    for (int kt = 0; kt < nk; kt++) {
        if (kt + 1 < nk) cp_wait<1>(); else cp_wait<0>();
        __syncthreads();
        if (kt + 2 < nk) issue(kt + 2);

        const unsigned sa = sA_u + (kt % 3) * GSTG;
        const unsigned sb = sB_u + (kt % 3) * GSTG;
#pragma unroll
        for (int ks = 0; ks < 4; ks++) {
            const unsigned kbb = ks * 32;
            unsigned af[4][4], bf[4][2];
#pragma unroll
            for (int mt = 0; mt < 4; mt++)
                LDSM4(af[mt][0], af[mt][1], af[mt][2], af[mt][3],
                      sa + a_off + mt * (16 * GKP * 2) + kbb);
#pragma unroll
            for (int p = 0; p < 2; p++)
                LDSM4(bf[2*p][0], bf[2*p][1], bf[2*p+1][0], bf[2*p+1][1],
                      sb + b_off + p * (16 * GKP * 2) + kbb);
#pragma unroll
            for (int mt = 0; mt < 4; mt++)
#pragma unroll
                for (int nt = 0; nt < 4; nt++)
                    mma_f16(acc[mt][nt], af[mt][0], af[mt][1], af[mt][2], af[mt][3],
                            bf[nt][0], bf[nt][1]);
        }
    }

#pragma unroll
    for (int mt = 0; mt < 4; mt++) {
        const int row = bm + wm + (mt << 4) + fr;
#pragma unroll
        for (int nt = 0; nt < 4; nt++) {
            const int col = bn + wn + (nt << 3) + (fc << 1);
            const float b0 = bias[col], b1 = bias[col + 1];
            if (HALF_OUT) {
                __half* C = (__half*)Cv;
                *(__half2*)(C + (size_t)row * N + col) =
                    __floats2half2_rn(acc[mt][nt][0] + b0, acc[mt][nt][1] + b1);
                *(__half2*)(C + (size_t)(row + 8) * N + col) =
                    __floats2half2_rn(acc[mt][nt][2] + b0, acc[mt][nt][3] + b1);
            } else {
                float* C = (float*)Cv;
                *(float2*)(C + (size_t)row * N + col) =
                    make_float2(acc[mt][nt][0] + b0, acc[mt][nt][1] + b1);
                *(float2*)(C + (size_t)(row + 8) * N + col) =
                    make_float2(acc[mt][nt][2] + b0, acc[mt][nt][3] + b1);
            }
        }
    }
}

// ---------------- RoPE + L2-norm + fp16 q/k + fp16 V transpose --------------
// sin/cos from precomputed table.
__global__ __launch_bounds__(128) void rope_kernel()
{
    __shared__ float sVt[64][65];
    const int tid = threadIdx.x;
    const int w = tid >> 5;
    const int f = tid & 31;
    const int blk = blockIdx.x;
    const int bh = blk >> 5;
    const int s0 = (blk & 31) << 6;
    const int b = bh >> 4, h = bh & 15;

#pragma unroll 1
    for (int t = 0; t < 16; t++) {
        const int sl = (w << 4) + t;
        const int s = s0 + sl;
        const float2 sc = g_sc[(s << 5) + f];
        const float sn = sc.x, cs = sc.y;

        const __half* src = g_qkv + (size_t)(b * SS + s) * N1 + h * HD;
        float2 qv = __half22float2(*(const __half2*)(src + 2 * f));
        float2 kv = __half22float2(*(const __half2*)(src + DD + 2 * f));
        float2 vv = __half22float2(*(const __half2*)(src + 2 * DD + 2 * f));

        const size_t dst = ((size_t)bh * SS + s) * HD + 2 * f;
        {
            float re = qv.x * cs - qv.y * sn;
            float ro = qv.x * sn + qv.y * cs;
            float sq = re * re + ro * ro;
#pragma unroll
            for (int msk = 16; msk > 0; msk >>= 1) sq += __shfl_xor_sync(0xffffffffu, sq, msk);
            float inv = (SCALE * LOG2E) / fmaxf(sqrtf(sq), 1e-12f);
            *(__half2*)(g_q + dst) = __floats2half2_rn(re * inv, ro * inv);
        }
        {
            float re = kv.x * cs - kv.y * sn;
            float ro = kv.x * sn + kv.y * cs;
            float sq = re * re + ro * ro;
#pragma unroll
            for (int msk = 16; msk > 0; msk >>= 1) sq += __shfl_xor_sync(0xffffffffu, sq, msk);
            float inv = 1.0f / fmaxf(sqrtf(sq), 1e-12f);
            *(__half2*)(g_k + dst) = __floats2half2_rn(re * inv, ro * inv);
        }
        sVt[sl][2 * f]     = vv.x;
        sVt[sl][2 * f + 1] = vv.y;
    }
    __syncthreads();

#pragma unroll 1
    for (int t = 0; t < 16; t++) {
        const int d = (w << 4) + t;
        __half* dst = g_v + ((size_t)bh * HD + d) * SS + s0;
        dst[f]      = __float2half_rn(sVt[f][d]);
        dst[f + 32] = __float2half_rn(sVt[f + 32][d]);
    }
}

// ---------------- flash attention: fixed-max softmax, 2-stage 64-kv tiles ---
// (round-11 structure: best measured attention at 110us)
#define KP2 72
#define KSTG (64 * KP2 * 2)                  // 9216 B
#define QSTG (128 * KP2 * 2)                 // 18432 B
#define ATTN_SMEM (4 * KSTG + QSTG)          // 55296 B

__global__ __launch_bounds__(256, 2) void attn_f16(__half* __restrict__ Oo)
{
    extern __shared__ __align__(16) unsigned smem_[];
    const unsigned sK_u = (unsigned)__cvta_generic_to_shared(smem_);
    const unsigned sV_u = sK_u + 2 * KSTG;
    const unsigned sQ_u = sK_u + 4 * KSTG;

    const int tid = threadIdx.x;
    const int w = tid >> 5;
    const int lane = tid & 31;
    const int fr = lane >> 2;
    const int fc = lane & 3;
    const int bh = blockIdx.y;
    const int b = bh >> 4, h = bh & 15;
    const int q0 = blockIdx.x << 7;

    const __half* Qp = g_q + (size_t)bh * SS * HD;
    const __half* Kp = g_k + (size_t)bh * SS * HD;
    const __half* Vp = g_v + (size_t)bh * HD * SS;

    const int krow = tid >> 2;               // 0..63
    const int kc = tid & 3;
    const int qrow = tid >> 1;               // 0..127
    const int qc = tid & 1;

    auto issueKV = [&](int jt) {
        const unsigned soK = sK_u + (jt & 1) * KSTG;
        const unsigned soV = sV_u + (jt & 1) * KSTG;
        const __half* gK = Kp + (size_t)(jt * 64 + krow) * HD;
        const __half* gV = Vp + (size_t)krow * SS + jt * 64;
#pragma unroll
        for (int t = 0; t < 2; t++) {
            const int c = (kc + (t << 2)) << 3;
            cp16(soK + (krow * KP2 + c) * 2, gK + c);
            cp16(soV + (krow * KP2 + c) * 2, gV + c);
        }
        cp_commit();
    };

    // stage Q, prefetch KV tile 0
    {
        const __half* gQ = Qp + (size_t)(q0 + qrow) * HD;
#pragma unroll
        for (int t = 0; t < 4; t++) {
            const int c = ((qc << 2) + t) << 3;
            cp16(sQ_u + (qrow * KP2 + c) * 2, gQ + c);
        }
        cp_commit();
    }
    issueKV(0);

    cp_wait<1>();      // Q resident (KV0 may still be in flight)
    __syncthreads();

    const unsigned a_q_off = (((w << 4) + (lane & 15)) * KP2 + ((lane >> 4) << 3)) * 2;
    unsigned qf[4][4];
#pragma unroll
    for (int ks = 0; ks < 4; ks++)
        LDSM4(qf[ks][0], qf[ks][1], qf[ks][2], qf[ks][3], sQ_u + a_q_off + ks * 32);

    const unsigned b_off = (((lane & 7) + ((lane >> 4) << 3)) * KP2
                            + (((lane >> 3) & 1) << 3)) * 2;

    float o[8][4];
#pragma unroll
    for (int nt = 0; nt < 8; nt++)
#pragma unroll
        for (int i = 0; i < 4; i++) o[nt][i] = 0.f;
    float lA = 0.f, lB = 0.f;     // plain row sums (fixed shift -> no max state)

    const int NT = SS / 64;
    for (int jt = 0; jt < NT; jt++) {
        cp_wait<0>();
        __syncthreads();
        if (jt + 1 < NT) issueKV(jt + 1);

        const unsigned Ktu = sK_u + (jt & 1) * KSTG;
        const unsigned Vtu = sV_u + (jt & 1) * KSTG;

        // S = Q K^T
        float s[8][4];
#pragma unroll
        for (int nt = 0; nt < 8; nt++)
#pragma unroll
            for (int i = 0; i < 4; i++) s[nt][i] = 0.f;
#pragma unroll
        for (int ks = 0; ks < 4; ks++) {
            unsigned bf[8][2];
#pragma unroll
            for (int ng = 0; ng < 4; ng++)
                LDSM4(bf[2*ng][0], bf[2*ng][1], bf[2*ng+1][0], bf[2*ng+1][1],
                      Ktu + b_off + ng * (16 * KP2 * 2) + ks * 32);
#pragma unroll
            for (int nt = 0; nt < 8; nt++)
                mma_f16(s[nt], qf[ks][0], qf[ks][1], qf[ks][2], qf[ks][3],
                        bf[nt][0], bf[nt][1]);
        }

        // p = exp2(s - M0); accumulate row sums; no rescale needed
#pragma unroll
        for (int nt = 0; nt < 8; nt++) {
            s[nt][0] = ex2(s[nt][0] - M0);
            s[nt][1] = ex2(s[nt][1] - M0);
            s[nt][2] = ex2(s[nt][2] - M0);
            s[nt][3] = ex2(s[nt][3] - M0);
            lA += s[nt][0] + s[nt][1];
            lB += s[nt][2] + s[nt][3];
        }

        // O += P @ V : P stays in registers (C-frag == A-frag)
#pragma unroll
        for (int ks = 0; ks < 4; ks++) {
            const unsigned a0 = pack_h2(s[2*ks][0],   s[2*ks][1]);
            const unsigned a1 = pack_h2(s[2*ks][2],   s[2*ks][3]);
            const unsigned a2 = pack_h2(s[2*ks+1][0], s[2*ks+1][1]);
            const unsigned a3 = pack_h2(s[2*ks+1][2], s[2*ks+1][3]);
            unsigned vf[8][2];
#pragma unroll
            for (int p = 0; p < 4; p++)
                LDSM4(vf[2*p][0], vf[2*p][1], vf[2*p+1][0], vf[2*p+1][1],
                      Vtu + b_off + p * (16 * KP2 * 2) + ks * 32);
#pragma unroll
            for (int nt = 0; nt < 8; nt++)
                mma_f16(o[nt], a0, a1, a2, a3, vf[nt][0], vf[nt][1]);
        }
    }

    // epilogue: deferred row-sum reduction, normalize, write fp16
    lA += __shfl_xor_sync(0xffffffffu, lA, 1);
    lA += __shfl_xor_sync(0xffffffffu, lA, 2);
    lB += __shfl_xor_sync(0xffffffffu, lB, 1);
    lB += __shfl_xor_sync(0xffffffffu, lB, 2);
    const float invA = 1.0f / lA;
    const float invB = 1.0f / lB;
    __half* Op = Oo + (size_t)b * SS * DD + h * HD;
    const int ra = q0 + (w << 4) + fr;
#pragma unroll
    for (int nt = 0; nt < 8; nt++) {
        const int col = (nt << 3) + (fc << 1);
        *(__half2*)(Op + (size_t)ra * DD + col) =
            __floats2half2_rn(o[nt][0] * invA, o[nt][1] * invA);
        *(__half2*)(Op + (size_t)(ra + 8) * DD + col) =
            __floats2half2_rn(o[nt][2] * invB, o[nt][3] * invB);
    }
}

// ---------------- launch ----------------------------------------------------
extern "C" void kernel_launch(void* const* d_in, const int* in_sizes, int n_in,
                              void* d_out, int out_size)
{
    (void)in_sizes; (void)n_in; (void)out_size;
    const float* tokens = (const float*)d_in[0];
    const float* qkv_w  = (const float*)d_in[1];
    const float* qkv_b  = (const float*)d_in[2];
    const float* out_w  = (const float*)d_in[3];
    const float* out_b  = (const float*)d_in[4];
    float* out = (float*)d_out;

    __half *qkv_s, *ao_s, *tokh, *wh, *owh;
    cudaGetSymbolAddress((void**)&qkv_s, g_qkv);
    cudaGetSymbolAddress((void**)&ao_s, g_ao);
    cudaGetSymbolAddress((void**)&tokh, g_tokh);
    cudaGetSymbolAddress((void**)&wh, g_wh);
    cudaGetSymbolAddress((void**)&owh, g_owh);

    static int smem_set = 0;
    if (!smem_set) {
        cudaFuncSetAttribute(gemm_f16_ldsm<true>, cudaFuncAttributeMaxDynamicSharedMemorySize, GEMM_SMEM);
        cudaFuncSetAttribute(gemm_f16_ldsm<false>, cudaFuncAttributeMaxDynamicSharedMemorySize, GEMM_SMEM);
        cudaFuncSetAttribute(attn_f16, cudaFuncAttributeMaxDynamicSharedMemorySize, ATTN_SMEM);
        smem_set = 1;
    }

    // 0) sin/cos table + fp16 operand conversion
    sincos_table_kernel<<<256, 256>>>();
    tohalf3_kernel<<<2048, 256>>>(
        (const float4*)tokens, (__half2*)tokh, M1 * KD / 4,
        (const float4*)qkv_w,  (__half2*)wh,   N1 * KD / 4,
        (const float4*)out_w,  (__half2*)owh,  DD * DD / 4);

    // 1) QKV projection
    gemm_f16_ldsm<true><<<dim3(N1 / 128, M1 / 128), 256, GEMM_SMEM>>>(
        tokh, wh, qkv_b, qkv_s, M1, N1, KD);
    // 2) RoPE (table) + normalize (+SCALE*log2e on q) + fp16 q/k/v + V transpose
    rope_kernel<<<NBH * (SS / 64), 128>>>();
    // 3) flash attention (fixed-max softmax, 2-stage 64-kv tiles)
    attn_f16<<<dim3(SS / 128, NBH), 256, ATTN_SMEM>>>(ao_s);
    // 4) output projection
    gemm_f16_ldsm<false><<<dim3(DD / 128, M1 / 128), 256, GEMM_SMEM>>>(
        ao_s, owh, out_b, out, M1, DD, KD);
}